// round 9
// baseline (speedup 1.0000x reference)
#include <cuda_runtime.h>
#include <stdint.h>

// CubeSpherePadding2D, p=1: [16,64,6,96,96] f32 -> [16,64,6,98,98] f32.
// Pure gather of the original input (reference's 24 sequential edge writes
// resolved analytically; rel_err==0 verified rounds 1-7).
//
// Layout (round 4, kept): thread t covers the SAME flat position in NJ slice
// blocks strided NSL_GRP apart (NSL_GRP % 6 == 0 -> same face, same edge
// case). Warp stores are flat-contiguous & 128B aligned; loads contiguous.
//
// Round-7 changes: NJ 8->16 (MLP 16, half the index math), streaming cache
// hints (__ldcs/__stcs) since the data streams with no reuse.

#define H 96
#define W 96
#define OH 98
#define OW 98
#define FACE (H * W)        // 9216
#define OFACE (OH * OW)     // 9604
#define NJ 16               // elements per thread
#define NSL_GRP 384         // slice stride between a thread's elements (6144/16)

__device__ __forceinline__ int src_off(int g, int y, int x) {
    return g * FACE + y * W + x;
}

// Source offset within the thread's 6-face block for an edge/corner output
// position (f, r, c). Returns -1 for the zero corners (faces 0-3).
__device__ __forceinline__ int edge_src_offset(int f, int r, int c) {
    bool rin = (unsigned)(r - 1) < 96u;
    bool cin = (unsigned)(c - 1) < 96u;

    if (rin && cin) {
        return src_off(f, r - 1, c - 1);
    }
    if (cin) {                              // top/bottom row, non-corner
        bool top = (r == 0);
        switch (f) {
            case 0: return top ? src_off(4, 95, c - 1)   : src_off(5, 0, c - 1);
            case 1: return top ? src_off(4, 96 - c, 95)  : src_off(5, c - 1, 95);
            case 2: return top ? src_off(4, 0, 96 - c)   : src_off(5, 95, 96 - c);
            case 3: return top ? src_off(4, c - 1, 0)    : src_off(5, 96 - c, 0);
            case 4: return top ? src_off(2, 0, 96 - c)   : src_off(0, 0, c - 1);
            default:return top ? src_off(0, 95, c - 1)   : src_off(2, 95, 96 - c);
        }
    }
    if (rin) {                              // left/right column, non-corner
        bool right = (c == 97);
        switch (f) {
            case 0: return right ? src_off(1, r - 1, 0)  : src_off(3, r - 1, 95);
            case 1: return right ? src_off(2, r - 1, 0)  : src_off(0, r - 1, 95);
            case 2: return right ? src_off(3, r - 1, 0)  : src_off(1, r - 1, 95);
            case 3: return right ? src_off(0, r - 1, 0)  : src_off(2, r - 1, 95);
            case 4: return right ? src_off(1, 0, 96 - r) : src_off(3, 0, r - 1);
            default:return right ? src_off(1, 95, r - 1) : src_off(3, 95, 96 - r);
        }
    }
    // corners: faces 0-3 read still-zero padding (reference assignment order);
    // faces 4,5 resolve depth-2 to original data.
    if (f == 4) {
        if (r == 0) return (c == 0) ? src_off(3, 0, 0)   : src_off(1, 0, 95);
        else        return (c == 0) ? src_off(3, 0, 95)  : src_off(1, 0, 0);
    }
    if (f == 5) {
        if (r == 0) return (c == 0) ? src_off(3, 95, 95) : src_off(1, 95, 0);
        else        return (c == 0) ? src_off(3, 95, 0)  : src_off(1, 95, 95);
    }
    return -1;
}

__global__ void __launch_bounds__(256)
cube_pad_sstride16_kernel(const float* __restrict__ in,
                          float* __restrict__ out,
                          int nthreads) {
    int t = blockIdx.x * blockDim.x + threadIdx.x;
    if (t >= nthreads) return;

    // Decompose within the first NSL_GRP-slice block; element j advances by
    // NSL_GRP slices (same face, same (r,c), same edge case).
    int slice0 = t / OFACE;             // 0..NSL_GRP-1
    int rem    = t - slice0 * OFACE;
    int r      = rem / OW;
    int c      = rem - r * OW;

    const long long S_IN  = (long long)NSL_GRP * FACE;    // 3,538,944
    const long long S_OUT = (long long)NSL_GRP * OFACE;   // 3,687,936

    float* __restrict__ op = out + t;   // flat: warp stores 128B aligned

    if ((unsigned)(r - 1) < 96u && (unsigned)(c - 1) < 96u) {
        // Interior: direct copy; lanes contiguous in c on both sides.
        const float* __restrict__ ip =
            in + (long long)slice0 * FACE + (r - 1) * W + (c - 1);
        float v[NJ];
        #pragma unroll
        for (int j = 0; j < NJ; ++j) v[j] = __ldcs(ip + j * S_IN);
        #pragma unroll
        for (int j = 0; j < NJ; ++j) __stcs(op + j * S_OUT, v[j]);
    } else {
        // Edge/corner: classify ONCE, apply to all NJ slices.
        int f   = slice0 % 6;
        int off = edge_src_offset(f, r, c);
        const float* __restrict__ B0 = in + (long long)(slice0 - f) * FACE;
        if (off >= 0) {
            float v[NJ];
            #pragma unroll
            for (int j = 0; j < NJ; ++j) v[j] = __ldcs(B0 + off + j * S_IN);
            #pragma unroll
            for (int j = 0; j < NJ; ++j) __stcs(op + j * S_OUT, v[j]);
        } else {
            #pragma unroll
            for (int j = 0; j < NJ; ++j) __stcs(op + j * S_OUT, 0.0f);
        }
    }
}

extern "C" void kernel_launch(void* const* d_in, const int* in_sizes, int n_in,
                              void* d_out, int out_size) {
    const float* in = (const float*)d_in[0];
    float* out = (float*)d_out;

    // out_size = 59,006,976 = 16 * 384 * 9604
    int nthreads = out_size / NJ;       // 3,687,936
    int threads = 256;
    int blocks = (nthreads + threads - 1) / threads;
    cube_pad_sstride16_kernel<<<blocks, threads>>>(in, out, nthreads);
}

// round 11
// speedup vs baseline: 1.0175x; 1.0175x over previous
#include <cuda_runtime.h>
#include <stdint.h>

// CubeSpherePadding2D, p=1: [16,64,6,96,96] f32 -> [16,64,6,98,98] f32.
// Pure gather of the original input (reference's 24 sequential edge writes
// resolved analytically; rel_err==0 verified rounds 1-9).
//
// Round-9 revert: back to the round-7 winner (NJ=8, plain ld/st — the NJ=16 +
// streaming-hint variant regressed: DRAM 71.6->67.5%, dur 76.9->80.0us).
// Only change vs round 7: block 256 -> 512.
//
// Layout: thread t covers the SAME flat position in 8 slice-blocks strided
// 768 slices apart (768 % 6 == 0 -> same face, same (r,c), same edge case).
// Warp accesses contiguous on both sides; stores flat-128B-aligned.

#define H 96
#define W 96
#define OH 98
#define OW 98
#define FACE (H * W)        // 9216
#define OFACE (OH * OW)     // 9604
#define NJ 8                // elements per thread
#define NSL_GRP 768         // slice stride between a thread's elements

__device__ __forceinline__ int src_off(int g, int y, int x) {
    return g * FACE + y * W + x;
}

// Source offset within the thread's 6-face block for an edge/corner output
// position (f, r, c). Returns -1 for the zero corners (faces 0-3).
__device__ __forceinline__ int edge_src_offset(int f, int r, int c) {
    bool rin = (unsigned)(r - 1) < 96u;
    bool cin = (unsigned)(c - 1) < 96u;

    if (rin && cin) {
        return src_off(f, r - 1, c - 1);
    }
    if (cin) {                              // top/bottom row, non-corner
        bool top = (r == 0);
        switch (f) {
            case 0: return top ? src_off(4, 95, c - 1)   : src_off(5, 0, c - 1);
            case 1: return top ? src_off(4, 96 - c, 95)  : src_off(5, c - 1, 95);
            case 2: return top ? src_off(4, 0, 96 - c)   : src_off(5, 95, 96 - c);
            case 3: return top ? src_off(4, c - 1, 0)    : src_off(5, 96 - c, 0);
            case 4: return top ? src_off(2, 0, 96 - c)   : src_off(0, 0, c - 1);
            default:return top ? src_off(0, 95, c - 1)   : src_off(2, 95, 96 - c);
        }
    }
    if (rin) {                              // left/right column, non-corner
        bool right = (c == 97);
        switch (f) {
            case 0: return right ? src_off(1, r - 1, 0)  : src_off(3, r - 1, 95);
            case 1: return right ? src_off(2, r - 1, 0)  : src_off(0, r - 1, 95);
            case 2: return right ? src_off(3, r - 1, 0)  : src_off(1, r - 1, 95);
            case 3: return right ? src_off(0, r - 1, 0)  : src_off(2, r - 1, 95);
            case 4: return right ? src_off(1, 0, 96 - r) : src_off(3, 0, r - 1);
            default:return right ? src_off(1, 95, r - 1) : src_off(3, 95, 96 - r);
        }
    }
    // corners: faces 0-3 read still-zero padding (reference assignment order);
    // faces 4,5 resolve depth-2 to original data.
    if (f == 4) {
        if (r == 0) return (c == 0) ? src_off(3, 0, 0)   : src_off(1, 0, 95);
        else        return (c == 0) ? src_off(3, 0, 95)  : src_off(1, 0, 0);
    }
    if (f == 5) {
        if (r == 0) return (c == 0) ? src_off(3, 95, 95) : src_off(1, 95, 0);
        else        return (c == 0) ? src_off(3, 95, 0)  : src_off(1, 95, 95);
    }
    return -1;
}

__global__ void __launch_bounds__(512)
cube_pad_sstride_kernel(const float* __restrict__ in,
                        float* __restrict__ out,
                        int nthreads) {
    int t = blockIdx.x * blockDim.x + threadIdx.x;
    if (t >= nthreads) return;

    int slice0 = t / OFACE;             // 0..767
    int rem    = t - slice0 * OFACE;
    int r      = rem / OW;
    int c      = rem - r * OW;

    const long long S_IN  = (long long)NSL_GRP * FACE;    // 7,077,888
    const long long S_OUT = (long long)NSL_GRP * OFACE;   // 7,375,872

    float* __restrict__ op = out + t;   // flat: warp stores 128B aligned

    if ((unsigned)(r - 1) < 96u && (unsigned)(c - 1) < 96u) {
        // Interior: direct copy; lanes contiguous in c on both sides.
        const float* __restrict__ ip =
            in + (long long)slice0 * FACE + (r - 1) * W + (c - 1);
        float v[NJ];
        #pragma unroll
        for (int j = 0; j < NJ; ++j) v[j] = __ldg(ip + j * S_IN);
        #pragma unroll
        for (int j = 0; j < NJ; ++j) op[j * S_OUT] = v[j];
    } else {
        // Edge/corner: classify ONCE, apply to all 8 slices.
        int f   = slice0 % 6;
        int off = edge_src_offset(f, r, c);
        const float* __restrict__ B0 = in + (long long)(slice0 - f) * FACE;
        if (off >= 0) {
            float v[NJ];
            #pragma unroll
            for (int j = 0; j < NJ; ++j) v[j] = __ldg(B0 + off + j * S_IN);
            #pragma unroll
            for (int j = 0; j < NJ; ++j) op[j * S_OUT] = v[j];
        } else {
            #pragma unroll
            for (int j = 0; j < NJ; ++j) op[j * S_OUT] = 0.0f;
        }
    }
}

extern "C" void kernel_launch(void* const* d_in, const int* in_sizes, int n_in,
                              void* d_out, int out_size) {
    const float* in = (const float*)d_in[0];
    float* out = (float*)d_out;

    // out_size = 59,006,976 = 8 * 768 * 9604
    int nthreads = out_size / NJ;       // 7,375,872
    int threads = 512;
    int blocks = (nthreads + threads - 1) / threads;
    cube_pad_sstride_kernel<<<blocks, threads>>>(in, out, nthreads);
}

// round 12
// speedup vs baseline: 1.0487x; 1.0306x over previous
#include <cuda_runtime.h>
#include <stdint.h>

// CubeSpherePadding2D, p=1: [16,64,6,96,96] f32 -> [16,64,6,98,98] f32.
// Pure gather of the original input (reference's 24 sequential edge writes
// resolved analytically; rel_err==0 verified rounds 1-11).
//
// Round-11 restructure: one CTA per slice. Assemble the full 98x98 output
// tile in SMEM (aligned LDG.128 interior + scalar edge gather), then write
// the slice as 2401 aligned STG.128 (slice output block = 38,416 B, 16B
// aligned, divisible by 16). This removes the +1-shift misalignment penalty
// and cuts memory instruction count ~4x on both sides.

#define H 96
#define W 96
#define OH 98
#define OW 98
#define FACE (H * W)        // 9216
#define OFACE (OH * OW)     // 9604
#define NSLICES 6144        // 16*64*6

__device__ __forceinline__ int src_off(int g, int y, int x) {
    return g * FACE + y * W + x;
}

// Source offset within the slice's 6-face block for a border output cell
// (f, r, c). Returns -1 for the zero corners (faces 0-3). Verified exact.
__device__ __forceinline__ int edge_src_offset(int f, int r, int c) {
    bool rin = (unsigned)(r - 1) < 96u;
    bool cin = (unsigned)(c - 1) < 96u;

    if (rin && cin) {
        return src_off(f, r - 1, c - 1);
    }
    if (cin) {                              // top/bottom row, non-corner
        bool top = (r == 0);
        switch (f) {
            case 0: return top ? src_off(4, 95, c - 1)   : src_off(5, 0, c - 1);
            case 1: return top ? src_off(4, 96 - c, 95)  : src_off(5, c - 1, 95);
            case 2: return top ? src_off(4, 0, 96 - c)   : src_off(5, 95, 96 - c);
            case 3: return top ? src_off(4, c - 1, 0)    : src_off(5, 96 - c, 0);
            case 4: return top ? src_off(2, 0, 96 - c)   : src_off(0, 0, c - 1);
            default:return top ? src_off(0, 95, c - 1)   : src_off(2, 95, 96 - c);
        }
    }
    if (rin) {                              // left/right column, non-corner
        bool right = (c == 97);
        switch (f) {
            case 0: return right ? src_off(1, r - 1, 0)  : src_off(3, r - 1, 95);
            case 1: return right ? src_off(2, r - 1, 0)  : src_off(0, r - 1, 95);
            case 2: return right ? src_off(3, r - 1, 0)  : src_off(1, r - 1, 95);
            case 3: return right ? src_off(0, r - 1, 0)  : src_off(2, r - 1, 95);
            case 4: return right ? src_off(1, 0, 96 - r) : src_off(3, 0, r - 1);
            default:return right ? src_off(1, 95, r - 1) : src_off(3, 95, 96 - r);
        }
    }
    // corners: faces 0-3 read still-zero padding (reference assignment order);
    // faces 4,5 resolve depth-2 to original data.
    if (f == 4) {
        if (r == 0) return (c == 0) ? src_off(3, 0, 0)   : src_off(1, 0, 95);
        else        return (c == 0) ? src_off(3, 0, 95)  : src_off(1, 0, 0);
    }
    if (f == 5) {
        if (r == 0) return (c == 0) ? src_off(3, 95, 95) : src_off(1, 95, 0);
        else        return (c == 0) ? src_off(3, 95, 0)  : src_off(1, 95, 95);
    }
    return -1;
}

__global__ void __launch_bounds__(256)
cube_pad_smem_kernel(const float* __restrict__ in,
                     float* __restrict__ out) {
    __shared__ __align__(16) float tile[OFACE];   // 38,416 B

    const int s   = blockIdx.x;                   // slice 0..6143
    const int tid = threadIdx.x;
    const int f   = s % 6;
    const float* __restrict__ B0 = in + (size_t)(s - f) * FACE;

    // Phase 1a: interior — 2304 aligned LDG.128, scalar STS shifted (+1,+1).
    const float4* __restrict__ in4 =
        reinterpret_cast<const float4*>(in + (size_t)s * FACE);
    #pragma unroll
    for (int i = tid; i < FACE / 4; i += 256) {   // 2304 -> 9 iters
        float4 v = __ldg(in4 + i);
        int row = i / (W / 4);
        int c4  = i - row * (W / 4);
        int b   = (row + 1) * OW + c4 * 4 + 1;
        tile[b]     = v.x;
        tile[b + 1] = v.y;
        tile[b + 2] = v.z;
        tile[b + 3] = v.w;
    }

    // Phase 1b: 388 border cells (two full rows incl. corners + two columns).
    for (int e = tid; e < 388; e += 256) {
        int r, c;
        if (e < 98)       { r = 0;            c = e;        }
        else if (e < 196) { r = 97;           c = e - 98;   }
        else if (e < 292) { r = 1 + (e - 196); c = 0;       }
        else              { r = 1 + (e - 292); c = 97;      }
        int off = edge_src_offset(f, r, c);
        tile[r * OW + c] = (off >= 0) ? __ldg(B0 + off) : 0.0f;
    }

    __syncthreads();

    // Phase 2: write the whole slice as aligned float4s (2401 per slice).
    float4* __restrict__ out4 =
        reinterpret_cast<float4*>(out) + (size_t)s * (OFACE / 4);
    const float4* __restrict__ t4 = reinterpret_cast<const float4*>(tile);
    #pragma unroll
    for (int i = tid; i < OFACE / 4; i += 256) {  // 2401 -> ~9.4 iters
        out4[i] = t4[i];
    }
}

extern "C" void kernel_launch(void* const* d_in, const int* in_sizes, int n_in,
                              void* d_out, int out_size) {
    const float* in = (const float*)d_in[0];
    float* out = (float*)d_out;

    cube_pad_smem_kernel<<<NSLICES, 256>>>(in, out);
}

// round 13
// speedup vs baseline: 1.1082x; 1.0568x over previous
#include <cuda_runtime.h>
#include <stdint.h>

// CubeSpherePadding2D, p=1: [16,64,6,96,96] f32 -> [16,64,6,98,98] f32.
// Pure gather of the original input (reference's 24 sequential edge writes
// resolved analytically; rel_err==0 verified rounds 1-12).
//
// Round-11 structure (kept): one CTA per slice; assemble the 98x98 tile in
// SMEM (aligned LDG.128 interior + scalar edge gather), then store the slice
// as 2401 aligned STG.128.
//
// Round-12 change: block 256 -> 512. With 38.4KB smem the CTA/SM limit is 5;
// at 256 threads that left 1280/2048 resident (occ 58%). At 512 threads the
// thread limit binds first: 4 CTAs x 512 = 2048 = full residency.

#define H 96
#define W 96
#define OH 98
#define OW 98
#define FACE (H * W)        // 9216
#define OFACE (OH * OW)     // 9604
#define NSLICES 6144        // 16*64*6
#define NT 512

__device__ __forceinline__ int src_off(int g, int y, int x) {
    return g * FACE + y * W + x;
}

// Source offset within the slice's 6-face block for a border output cell
// (f, r, c). Returns -1 for the zero corners (faces 0-3). Verified exact.
__device__ __forceinline__ int edge_src_offset(int f, int r, int c) {
    bool rin = (unsigned)(r - 1) < 96u;
    bool cin = (unsigned)(c - 1) < 96u;

    if (rin && cin) {
        return src_off(f, r - 1, c - 1);
    }
    if (cin) {                              // top/bottom row, non-corner
        bool top = (r == 0);
        switch (f) {
            case 0: return top ? src_off(4, 95, c - 1)   : src_off(5, 0, c - 1);
            case 1: return top ? src_off(4, 96 - c, 95)  : src_off(5, c - 1, 95);
            case 2: return top ? src_off(4, 0, 96 - c)   : src_off(5, 95, 96 - c);
            case 3: return top ? src_off(4, c - 1, 0)    : src_off(5, 96 - c, 0);
            case 4: return top ? src_off(2, 0, 96 - c)   : src_off(0, 0, c - 1);
            default:return top ? src_off(0, 95, c - 1)   : src_off(2, 95, 96 - c);
        }
    }
    if (rin) {                              // left/right column, non-corner
        bool right = (c == 97);
        switch (f) {
            case 0: return right ? src_off(1, r - 1, 0)  : src_off(3, r - 1, 95);
            case 1: return right ? src_off(2, r - 1, 0)  : src_off(0, r - 1, 95);
            case 2: return right ? src_off(3, r - 1, 0)  : src_off(1, r - 1, 95);
            case 3: return right ? src_off(0, r - 1, 0)  : src_off(2, r - 1, 95);
            case 4: return right ? src_off(1, 0, 96 - r) : src_off(3, 0, r - 1);
            default:return right ? src_off(1, 95, r - 1) : src_off(3, 95, 96 - r);
        }
    }
    // corners: faces 0-3 read still-zero padding (reference assignment order);
    // faces 4,5 resolve depth-2 to original data.
    if (f == 4) {
        if (r == 0) return (c == 0) ? src_off(3, 0, 0)   : src_off(1, 0, 95);
        else        return (c == 0) ? src_off(3, 0, 95)  : src_off(1, 0, 0);
    }
    if (f == 5) {
        if (r == 0) return (c == 0) ? src_off(3, 95, 95) : src_off(1, 95, 0);
        else        return (c == 0) ? src_off(3, 95, 0)  : src_off(1, 95, 95);
    }
    return -1;
}

__global__ void __launch_bounds__(NT)
cube_pad_smem_kernel(const float* __restrict__ in,
                     float* __restrict__ out) {
    __shared__ __align__(16) float tile[OFACE];   // 38,416 B

    const int s   = blockIdx.x;                   // slice 0..6143
    const int tid = threadIdx.x;
    const int f   = s % 6;
    const float* __restrict__ B0 = in + (size_t)(s - f) * FACE;

    // Phase 1a: interior — 2304 aligned LDG.128, scalar STS shifted (+1,+1).
    const float4* __restrict__ in4 =
        reinterpret_cast<const float4*>(in + (size_t)s * FACE);
    #pragma unroll
    for (int i = tid; i < FACE / 4; i += NT) {    // 2304 -> 4.5 iters
        float4 v = __ldg(in4 + i);
        int row = i / (W / 4);
        int c4  = i - row * (W / 4);
        int b   = (row + 1) * OW + c4 * 4 + 1;
        tile[b]     = v.x;
        tile[b + 1] = v.y;
        tile[b + 2] = v.z;
        tile[b + 3] = v.w;
    }

    // Phase 1b: 388 border cells (two full rows incl. corners + two columns).
    for (int e = tid; e < 388; e += NT) {
        int r, c;
        if (e < 98)       { r = 0;             c = e;      }
        else if (e < 196) { r = 97;            c = e - 98; }
        else if (e < 292) { r = 1 + (e - 196); c = 0;      }
        else              { r = 1 + (e - 292); c = 97;     }
        int off = edge_src_offset(f, r, c);
        tile[r * OW + c] = (off >= 0) ? __ldg(B0 + off) : 0.0f;
    }

    __syncthreads();

    // Phase 2: write the whole slice as aligned float4s (2401 per slice).
    float4* __restrict__ out4 =
        reinterpret_cast<float4*>(out) + (size_t)s * (OFACE / 4);
    const float4* __restrict__ t4 = reinterpret_cast<const float4*>(tile);
    #pragma unroll
    for (int i = tid; i < OFACE / 4; i += NT) {   // 2401 -> ~4.7 iters
        out4[i] = t4[i];
    }
}

extern "C" void kernel_launch(void* const* d_in, const int* in_sizes, int n_in,
                              void* d_out, int out_size) {
    const float* in = (const float*)d_in[0];
    float* out = (float*)d_out;

    cube_pad_smem_kernel<<<NSLICES, NT>>>(in, out);
}